// round 17
// baseline (speedup 1.0000x reference)
#include <cuda_runtime.h>

// Merton jump diffusion — per-warp scan, rolling quarter-interleaved prefetch for
// zd/n, PREDICATED z_jump loads behind a warp-uniform ballot skip (~88% of
// quarters do zero zj work), and 2-chunk (64-col) SMEM staging so each output
// row drains as a 256B contiguous train (less unaligned-sector amplification).
//   paths[p,0]   = S0
//   paths[p,t+1] = S0 * exp( sum_{u<=t} drift[u] + CDIFF*zd[u,p] + sqrt(nj[u,p])*0.3*zj[u,p] )

#define N_STEPS   2048
#define N_PATHS   32768
#define TPB       64
#define WARPS     (TPB / 32)
#define TILE      32
#define QUART     8
#define N_CHUNKS  (N_STEPS / TILE)       // 64
#define OUT_COLS  (N_STEPS + 1)
#define JT_SIZE   32
#define ROWPAD    68                     // 64 cols + 4 pad; fill/drain conflict-free

__global__ __launch_bounds__(TPB) void merton_kernel(
    const float* __restrict__ S0p,
    const float* __restrict__ zd,
    const float* __restrict__ zj,
    const int*   __restrict__ njp,
    float*       __restrict__ out)
{
    __shared__ float drift_s[N_STEPS];               // 8 KB, broadcast reads
    __shared__ float jtab[JT_SIZE];
    __shared__ float tbuf[WARPS][TILE][ROWPAD];      // 17.4 KB: 2-chunk tiles

    const int tid   = threadIdx.x;
    const int lane  = tid & 31;
    const int warp  = tid >> 5;
    const int wbase = blockIdx.x * TPB + warp * 32;  // warp's first path
    const int p     = wbase + lane;

    const float DT    = 1.0f / 2048.0f;
    const float KAPPA = 0.04602785990f;              // exp(0.045) - 1 (fp32)
    const float CDIFF = 0.2f * 0.02209708691f;       // SIGMA * fl(sqrt(DT)), ref fp32 order

    for (int i = tid; i < N_STEPS; i += TPB) {
        float t   = (float)i * DT;
        float lam = 0.1f + 0.9f * expf(-0.01f * t);
        drift_s[i] = (0.0f - lam * KAPPA) * DT;
    }
    if (tid < JT_SIZE) jtab[tid] = sqrtf((float)tid) * 0.3f;

    const float s0 = S0p[0];
    __syncthreads();                                 // one-time: tables ready

    out[p * OUT_COLS] = s0;                          // column 0

    // Rolling register buffers: zd + n unconditional, zj conditional (n>0 only)
    float r1[TILE], r2[TILE];
    int   r3[TILE];

    #pragma unroll
    for (int s = 0; s < TILE; ++s) r2[s] = 0.0f;

    // Prologue: chunk 0 zd + n, then conditional zj for quarter 0
    #pragma unroll
    for (int s = 0; s < TILE; ++s) {
        const int idx = s * N_PATHS + p;
        r1[s] = __ldcs(zd + idx);
        r3[s] = __ldcs(njp + idx);
    }
    {
        bool any = false;
        #pragma unroll
        for (int s = 0; s < QUART; ++s) any |= (r3[s] > 0);
        if (__any_sync(0xffffffffu, any)) {
            #pragma unroll
            for (int s = 0; s < QUART; ++s)
                if (r3[s] > 0) r2[s] = __ldcs(zj + s * N_PATHS + p);
        }
    }

    float acc = 0.0f;
    float v[TILE];

    for (int c = 0; c < N_CHUNKS; ++c) {
        const int tb = c * TILE;

        #pragma unroll
        for (int q = 0; q < 4; ++q) {
            // --- Compute quarter q (r2 valid wherever n>0; gated select otherwise) ---
            #pragma unroll
            for (int k = 0; k < QUART; ++k) {
                const int s = q * QUART + k;
                int n = r3[s];
                int nc = (n < JT_SIZE) ? n : (JT_SIZE - 1);
                float jterm = (n > 0) ? jtab[nc] * r2[s] : 0.0f;
                acc += drift_s[tb + s] + CDIFF * r1[s] + jterm;
                v[s] = s0 * __expf(acc);
            }

            // --- Refill just-freed quarter with next chunk's zd + n ---
            if (c + 1 < N_CHUNKS) {
                #pragma unroll
                for (int k = 0; k < QUART; ++k) {
                    const int s   = q * QUART + k;
                    const int idx = (tb + TILE + s) * N_PATHS + p;
                    r1[s] = __ldcs(zd + idx);
                    r3[s] = __ldcs(njp + idx);
                }
            }

            // --- Conditional zj prefetch for the NEXT quarter, ballot-skipped ---
            // q<3: quarter q+1 of this chunk. q==3: quarter 0 of chunk c+1
            // (r3 slots 0..7 were refilled at q=0, loads long since arrived).
            if (q < 3 || c + 1 < N_CHUNKS) {
                const int nq    = (q + 1) & 3;
                const int cbase = (q < 3) ? tb : (tb + TILE);
                bool any = false;
                #pragma unroll
                for (int k = 0; k < QUART; ++k) any |= (r3[nq * QUART + k] > 0);
                if (__any_sync(0xffffffffu, any)) {            // ~12% of quarters
                    #pragma unroll
                    for (int k = 0; k < QUART; ++k) {
                        const int s2 = nq * QUART + k;
                        if (r3[s2] > 0) r2[s2] = __ldcs(zj + (cbase + s2) * N_PATHS + p);
                    }
                }
            }
        }

        // Stage this chunk into its half of the 64-col tile (STS.128, conflict-free)
        const int half = (c & 1) * TILE;
        #pragma unroll
        for (int s = 0; s < TILE; s += 4) {
            *reinterpret_cast<float4*>(&tbuf[warp][lane][half + s]) =
                make_float4(v[s], v[s + 1], v[s + 2], v[s + 3]);
        }
        __syncwarp();

        // Drain every 2 chunks: each output row gets a 256B contiguous store train
        if (c & 1) {
            const int colbase = (c - 1) * TILE;
            #pragma unroll
            for (int j = 0; j < TILE; ++j) {
                const float* row = &tbuf[warp][j][0];
                float* orow = &out[(wbase + j) * OUT_COLS + 1 + colbase];
                __stcs(orow + lane,      row[lane]);
                __stcs(orow + 32 + lane, row[32 + lane]);
            }
            __syncwarp();                            // WAR before reusing the tile
        }
    }
}

extern "C" void kernel_launch(void* const* d_in, const int* in_sizes, int n_in,
                              void* d_out, int out_size)
{
    const float* S0 = (const float*)d_in[0];
    const float* zd = (const float*)d_in[1];
    const float* zj = (const float*)d_in[2];
    const int*   nj = (const int*)  d_in[3];
    float*       out = (float*)d_out;

    merton_kernel<<<N_PATHS / TPB, TPB>>>(S0, zd, zj, nj, out);
}